// round 10
// baseline (speedup 1.0000x reference)
#include <cuda_runtime.h>
#include <cuda_bf16.h>
#include <cstdint>

#define B_SZ 2048
#define H_SZ 2048
#define P_SZ 8192
#define K_TOTAL 2048

// ---------------------------------------------------------------------------
// Scratch (__device__ globals; no cudaMalloc allowed)
// ---------------------------------------------------------------------------
__device__ __align__(1024) float g_proj[(size_t)B_SZ * 3 * H_SZ];
__device__ __align__(1024) __nv_bfloat16 g_hid_hi[(size_t)B_SZ * H_SZ];
__device__ __align__(1024) __nv_bfloat16 g_hid_lo[(size_t)B_SZ * H_SZ];
__device__ __align__(1024) __nv_bfloat16 g_win_hi[(size_t)3 * H_SZ * H_SZ];
__device__ __align__(1024) __nv_bfloat16 g_win_lo[(size_t)3 * H_SZ * H_SZ];
__device__ __align__(1024) __nv_bfloat16 g_wout_hi[(size_t)H_SZ * H_SZ];
__device__ __align__(1024) __nv_bfloat16 g_wout_lo[(size_t)H_SZ * H_SZ];
__device__ __align__(1024) __nv_bfloat16 g_gated_hi[(size_t)B_SZ * H_SZ];
__device__ __align__(1024) __nv_bfloat16 g_gated_lo[(size_t)B_SZ * H_SZ];

// ---------------------------------------------------------------------------
// Baseline-PTX helpers (legal on plain sm_103 target)
// ---------------------------------------------------------------------------
__device__ __forceinline__ uint32_t smem_u32(const void* p) {
    uint32_t a;
    asm("{ .reg .u64 t; cvta.to.shared.u64 t, %1; cvt.u32.u64 %0, t; }"
        : "=r"(a) : "l"(p));
    return a;
}

__device__ __forceinline__ void cp16(uint32_t dst, const void* src) {
    asm volatile("cp.async.cg.shared.global [%0], [%1], 16;"
                 :: "r"(dst), "l"(src));
}
#define CP_COMMIT() asm volatile("cp.async.commit_group;" ::: "memory")
#define CP_WAIT1()  asm volatile("cp.async.wait_group 1;" ::: "memory")

__device__ __forceinline__ void ldsm_x4(uint32_t* r, uint32_t addr) {
    asm volatile("ldmatrix.sync.aligned.m8n8.x4.shared.b16 {%0,%1,%2,%3}, [%4];"
                 : "=r"(r[0]), "=r"(r[1]), "=r"(r[2]), "=r"(r[3]) : "r"(addr));
}

__device__ __forceinline__ void mma_bf16(float* c, const uint32_t* a,
                                         const uint32_t* b) {
    asm volatile(
        "mma.sync.aligned.m16n8k16.row.col.f32.bf16.bf16.f32 "
        "{%0,%1,%2,%3}, {%4,%5,%6,%7}, {%8,%9}, {%0,%1,%2,%3};"
        : "+f"(c[0]), "+f"(c[1]), "+f"(c[2]), "+f"(c[3])
        : "r"(a[0]), "r"(a[1]), "r"(a[2]), "r"(a[3]), "r"(b[0]), "r"(b[1]));
}

// ---------------------------------------------------------------------------
// Split-bf16 warp-MMA GEMM: C[m,n] = sum_k A[m,k]*B[n,k], fp32-emulated via
// D += Ah*Bh + Al*Bh + Ah*Bl. CTA tile 128M x 256N, BK=32, 3-stage cp.async.
// Stage layout: Ah@0 (8K), Al@8K, Bh@16K (16K), Bl@32K (16K) -> 48KB/stage.
// Each tile row is 64B with XOR swizzle off(r,c4)=r*64+((c4^((r>>1)&3))<<4).
// 8 warps: wm = wid&1 (64 M-rows each), wn = wid>>1 (64 N-cols each).
// ---------------------------------------------------------------------------
#define BKI 32
#define NIT (K_TOTAL / BKI)          // 64
#define STG_BYTES 49152
#define NSTG 3
#define SMEM_TOTAL (NSTG * STG_BYTES)
#define OFF_AL 8192
#define OFF_BH 16384
#define OFF_BL 32768

__global__ __launch_bounds__(256)
void mma_gemm_kernel(const __nv_bfloat16* __restrict__ Ah,
                     const __nv_bfloat16* __restrict__ Al,
                     const __nv_bfloat16* __restrict__ Bh,
                     const __nv_bfloat16* __restrict__ Bl,
                     float* __restrict__ C, int Ntotal) {
    extern __shared__ __align__(1024) char smem[];
    const uint32_t sb = smem_u32(smem);
    const int tid = threadIdx.x;
    const int lane = tid & 31;
    const int wid = tid >> 5;
    const int wm = wid & 1;            // 2 warps along M (64 rows each)
    const int wn = wid >> 1;           // 4 warps along N (64 cols each)
    const int mBase = blockIdx.y * 128;
    const int nBase = blockIdx.x * 256;

    // ---- cp.async mapping: A 2 reps, B 4 reps of 64 rows; 12 cp16/thread ----
    const int ldRow = tid >> 2;        // 0..63
    const int ldC4 = tid & 3;
    const uint32_t sOff =
        (uint32_t)ldRow * 64 + ((((uint32_t)ldC4) ^ ((ldRow >> 1) & 3)) << 4);
    const size_t gRep = (size_t)64 * K_TOTAL;
    const __nv_bfloat16* gAh = Ah + (size_t)(mBase + ldRow) * K_TOTAL + ldC4 * 8;
    const __nv_bfloat16* gAl = Al + (size_t)(mBase + ldRow) * K_TOTAL + ldC4 * 8;
    const __nv_bfloat16* gBh = Bh + (size_t)(nBase + ldRow) * K_TOTAL + ldC4 * 8;
    const __nv_bfloat16* gBl = Bl + (size_t)(nBase + ldRow) * K_TOTAL + ldC4 * 8;

#define ISSUE(sst, k0) do {                                                    \
        cp16((sst) + sOff,                     gAh + (k0));                     \
        cp16((sst) + sOff + 4096,              gAh + (k0) + gRep);              \
        cp16((sst) + OFF_AL + sOff,            gAl + (k0));                     \
        cp16((sst) + OFF_AL + sOff + 4096,     gAl + (k0) + gRep);              \
        cp16((sst) + OFF_BH + sOff,            gBh + (k0));                     \
        cp16((sst) + OFF_BH + sOff + 4096,     gBh + (k0) + gRep);              \
        cp16((sst) + OFF_BH + sOff + 8192,     gBh + (k0) + 2 * gRep);          \
        cp16((sst) + OFF_BH + sOff + 12288,    gBh + (k0) + 3 * gRep);          \
        cp16((sst) + OFF_BL + sOff,            gBl + (k0));                     \
        cp16((sst) + OFF_BL + sOff + 4096,     gBl + (k0) + gRep);              \
        cp16((sst) + OFF_BL + sOff + 8192,     gBl + (k0) + 2 * gRep);          \
        cp16((sst) + OFF_BL + sOff + 12288,    gBl + (k0) + 3 * gRep);          \
    } while (0)

    // ---- ldmatrix per-thread pre-offsets ----
    uint32_t aBase[4], aSw[4];
    const int rA = lane & 15;
#pragma unroll
    for (int i = 0; i < 4; i++) {
        int row = wm * 64 + i * 16 + rA;
        aBase[i] = (uint32_t)row * 64;
        aSw[i] = (row >> 1) & 3;
    }
    const uint32_t aK = (uint32_t)(lane >> 4);        // 0/1
    uint32_t bBase[4], bSw[4];
    const int rB = (lane & 7) + ((lane & 16) ? 8 : 0);
#pragma unroll
    for (int p = 0; p < 4; p++) {
        int row = wn * 64 + p * 16 + rB;
        bBase[p] = (uint32_t)row * 64;
        bSw[p] = (row >> 1) & 3;
    }
    const uint32_t bK = (uint32_t)((lane >> 3) & 1);

    float acc[4][8][4];
#pragma unroll
    for (int i = 0; i < 4; i++)
#pragma unroll
        for (int j = 0; j < 8; j++)
#pragma unroll
            for (int v = 0; v < 4; v++) acc[i][j][v] = 0.f;

    // ---- pipeline prologue ----
    ISSUE(sb + 0 * STG_BYTES, 0);
    CP_COMMIT();
    ISSUE(sb + 1 * STG_BYTES, BKI);
    CP_COMMIT();

    for (int it = 0; it < NIT; ++it) {
        CP_WAIT1();
        __syncthreads();

        if (it + 2 < NIT) {
            uint32_t sn = sb + ((it + 2) % NSTG) * STG_BYTES;
            ISSUE(sn, (it + 2) * BKI);
        }
        CP_COMMIT();

        const uint32_t sst = sb + (it % NSTG) * STG_BYTES;
#pragma unroll
        for (int kk = 0; kk < 2; kk++) {           // two k16 halves of BK=32
            const uint32_t kc = (uint32_t)(kk * 2);
            uint32_t af[16], af2[16], bf[16];

            // Ah, Bh
#pragma unroll
            for (int i = 0; i < 4; i++)
                ldsm_x4(&af[i * 4],
                        sst + aBase[i] + (((aK + kc) ^ aSw[i]) << 4));
#pragma unroll
            for (int p = 0; p < 4; p++)
                ldsm_x4(&bf[p * 4],
                        sst + OFF_BH + bBase[p] + (((bK + kc) ^ bSw[p]) << 4));
#pragma unroll
            for (int i = 0; i < 4; i++)
#pragma unroll
                for (int j = 0; j < 8; j++)
                    mma_bf16(acc[i][j], &af[i * 4],
                             &bf[(j >> 1) * 4 + (j & 1) * 2]);

            // Al * Bh
#pragma unroll
            for (int i = 0; i < 4; i++)
                ldsm_x4(&af2[i * 4],
                        sst + OFF_AL + aBase[i] + (((aK + kc) ^ aSw[i]) << 4));
#pragma unroll
            for (int i = 0; i < 4; i++)
#pragma unroll
                for (int j = 0; j < 8; j++)
                    mma_bf16(acc[i][j], &af2[i * 4],
                             &bf[(j >> 1) * 4 + (j & 1) * 2]);

            // Ah * Bl (overwrite bf with Bl; af still holds Ah)
#pragma unroll
            for (int p = 0; p < 4; p++)
                ldsm_x4(&bf[p * 4],
                        sst + OFF_BL + bBase[p] + (((bK + kc) ^ bSw[p]) << 4));
#pragma unroll
            for (int i = 0; i < 4; i++)
#pragma unroll
                for (int j = 0; j < 8; j++)
                    mma_bf16(acc[i][j], &af[i * 4],
                             &bf[(j >> 1) * 4 + (j & 1) * 2]);
        }
        __syncthreads();
    }

    // ---- epilogue: write C ----
    const int row0 = mBase + wm * 64 + (lane >> 2);
    const int col0 = nBase + wn * 64 + (lane & 3) * 2;
#pragma unroll
    for (int i = 0; i < 4; i++) {
#pragma unroll
        for (int j = 0; j < 8; j++) {
            float* p0 = C + (size_t)(row0 + i * 16) * Ntotal + col0 + j * 8;
            float* p1 = p0 + (size_t)8 * Ntotal;
            *(float2*)p0 = make_float2(acc[i][j][0], acc[i][j][1]);
            *(float2*)p1 = make_float2(acc[i][j][2], acc[i][j][3]);
        }
    }
#undef ISSUE
}

// ---------------------------------------------------------------------------
// fp32 -> (bf16 hi, bf16 lo) split
// ---------------------------------------------------------------------------
__global__ void split_bf16_kernel(const float* __restrict__ src,
                                  __nv_bfloat16* __restrict__ hi,
                                  __nv_bfloat16* __restrict__ lo, int n) {
    int i = blockIdx.x * blockDim.x + threadIdx.x;
    int stride = gridDim.x * blockDim.x;
    for (; i < n; i += stride) {
        float v = src[i];
        __nv_bfloat16 h = __float2bfloat16(v);
        hi[i] = h;
        lo[i] = __float2bfloat16(v - __bfloat162float(h));
    }
}

// ---------------------------------------------------------------------------
// conv_state copy-through
// ---------------------------------------------------------------------------
__global__ void copy_state_kernel(const float4* __restrict__ src,
                                  float4* __restrict__ dst, int n4) {
    int i = blockIdx.x * blockDim.x + threadIdx.x;
    int stride = gridDim.x * blockDim.x;
    for (; i < n4; i += stride) dst[i] = src[i];
}

// ---------------------------------------------------------------------------
// conv + gating epilogue; emits gated as bf16 hi/lo splits directly
// ---------------------------------------------------------------------------
__global__ void conv_epilogue_kernel(const float* __restrict__ proj,
                                     const float* __restrict__ conv_state,
                                     const int* __restrict__ idx,
                                     const float* __restrict__ conv_w,
                                     __nv_bfloat16* __restrict__ ghi,
                                     __nv_bfloat16* __restrict__ glo,
                                     float* __restrict__ out_state) {
    int i = blockIdx.x * blockDim.x + threadIdx.x;
    if (i >= B_SZ * H_SZ) return;
    int b = i >> 11;
    int h = i & (H_SZ - 1);
    int r = idx[b];

    const float* cs = conv_state + ((size_t)r * H_SZ + h) * 3;
    float c0 = cs[0], c1 = cs[1], c2 = cs[2];

    const float* prow = proj + (size_t)b * 3 * H_SZ;
    float Bg = prow[h];
    float Cg = prow[H_SZ + h];
    float x  = prow[2 * H_SZ + h];
    float Bx = Bg * x;

    const float* w = conv_w + h * 4;
    float conv_out = fmaf(c0, w[0], fmaf(c1, w[1], fmaf(c2, w[2], Bx * w[3])));
    float g = Cg * conv_out;

    __nv_bfloat16 gh = __float2bfloat16(g);
    ghi[i] = gh;
    glo[i] = __float2bfloat16(g - __bfloat162float(gh));

    float* os = out_state + ((size_t)r * H_SZ + h) * 3;
    os[0] = c1;
    os[1] = c2;
    os[2] = Bx;
}

// ---------------------------------------------------------------------------
extern "C" void kernel_launch(void* const* d_in, const int* in_sizes, int n_in,
                              void* d_out, int out_size) {
    const float* hidden     = (const float*)d_in[0];
    const float* conv_state = (const float*)d_in[1];
    const int*   idx        = (const int*)d_in[2];
    const float* w_in       = (const float*)d_in[3];
    const float* w_out      = (const float*)d_in[4];
    const float* conv_w     = (const float*)d_in[5];

    float* y         = (float*)d_out;
    float* out_state = y + (size_t)B_SZ * H_SZ;

    void *proj, *hid_hi, *hid_lo, *win_hi, *win_lo, *wout_hi, *wout_lo,
         *gat_hi, *gat_lo;
    cudaGetSymbolAddress(&proj, g_proj);
    cudaGetSymbolAddress(&hid_hi, g_hid_hi);
    cudaGetSymbolAddress(&hid_lo, g_hid_lo);
    cudaGetSymbolAddress(&win_hi, g_win_hi);
    cudaGetSymbolAddress(&win_lo, g_win_lo);
    cudaGetSymbolAddress(&wout_hi, g_wout_hi);
    cudaGetSymbolAddress(&wout_lo, g_wout_lo);
    cudaGetSymbolAddress(&gat_hi, g_gated_hi);
    cudaGetSymbolAddress(&gat_lo, g_gated_lo);

    cudaFuncSetAttribute(mma_gemm_kernel,
                         cudaFuncAttributeMaxDynamicSharedMemorySize,
                         SMEM_TOTAL);

    // 1) bf16 hi/lo splits of inputs/weights
    split_bf16_kernel<<<2048, 256>>>(hidden, (__nv_bfloat16*)hid_hi,
                                     (__nv_bfloat16*)hid_lo, B_SZ * H_SZ);
    split_bf16_kernel<<<4096, 256>>>(w_in, (__nv_bfloat16*)win_hi,
                                     (__nv_bfloat16*)win_lo, 3 * H_SZ * H_SZ);
    split_bf16_kernel<<<2048, 256>>>(w_out, (__nv_bfloat16*)wout_hi,
                                     (__nv_bfloat16*)wout_lo, H_SZ * H_SZ);

    // 2) conv_state copy-through (rows overwritten by epilogue)
    copy_state_kernel<<<4096, 256>>>((const float4*)conv_state,
                                     (float4*)out_state, (P_SZ * H_SZ * 3) / 4);

    // 3) proj = hidden @ w_in^T   [2048 x 6144]
    mma_gemm_kernel<<<dim3((3 * H_SZ) / 256, B_SZ / 128), 256, SMEM_TOTAL>>>(
        (const __nv_bfloat16*)hid_hi, (const __nv_bfloat16*)hid_lo,
        (const __nv_bfloat16*)win_hi, (const __nv_bfloat16*)win_lo,
        (float*)proj, 3 * H_SZ);

    // 4) conv + gate epilogue -> gated (bf16 hi/lo), scatter state rows
    conv_epilogue_kernel<<<(B_SZ * H_SZ + 255) / 256, 256>>>(
        (const float*)proj, conv_state, idx, conv_w,
        (__nv_bfloat16*)gat_hi, (__nv_bfloat16*)gat_lo, out_state);

    // 5) y = gated @ w_out^T   [2048 x 2048]
    mma_gemm_kernel<<<dim3(H_SZ / 256, B_SZ / 128), 256, SMEM_TOTAL>>>(
        (const __nv_bfloat16*)gat_hi, (const __nv_bfloat16*)gat_lo,
        (const __nv_bfloat16*)wout_hi, (const __nv_bfloat16*)wout_lo,
        y, H_SZ);
}

// round 11
// speedup vs baseline: 1.0025x; 1.0025x over previous
#include <cuda_runtime.h>
#include <cuda_bf16.h>
#include <cstdint>

#define B_SZ 2048
#define H_SZ 2048
#define P_SZ 8192
#define K_TOTAL 2048

// ---------------------------------------------------------------------------
// Scratch (__device__ globals; no cudaMalloc allowed)
// ---------------------------------------------------------------------------
__device__ __align__(1024) float g_proj[(size_t)B_SZ * 3 * H_SZ];
__device__ __align__(1024) __nv_bfloat16 g_hid_hi[(size_t)B_SZ * H_SZ];
__device__ __align__(1024) __nv_bfloat16 g_hid_lo[(size_t)B_SZ * H_SZ];
__device__ __align__(1024) __nv_bfloat16 g_win_hi[(size_t)3 * H_SZ * H_SZ];
__device__ __align__(1024) __nv_bfloat16 g_win_lo[(size_t)3 * H_SZ * H_SZ];
__device__ __align__(1024) __nv_bfloat16 g_wout_hi[(size_t)H_SZ * H_SZ];
__device__ __align__(1024) __nv_bfloat16 g_wout_lo[(size_t)H_SZ * H_SZ];
__device__ __align__(1024) __nv_bfloat16 g_gated_hi[(size_t)B_SZ * H_SZ];
__device__ __align__(1024) __nv_bfloat16 g_gated_lo[(size_t)B_SZ * H_SZ];

// ---------------------------------------------------------------------------
// Baseline-PTX helpers (legal on plain sm_103 target)
// ---------------------------------------------------------------------------
__device__ __forceinline__ uint32_t smem_u32(const void* p) {
    uint32_t a;
    asm("{ .reg .u64 t; cvta.to.shared.u64 t, %1; cvt.u32.u64 %0, t; }"
        : "=r"(a) : "l"(p));
    return a;
}

__device__ __forceinline__ void cp16(uint32_t dst, const void* src) {
    asm volatile("cp.async.cg.shared.global [%0], [%1], 16;"
                 :: "r"(dst), "l"(src));
}
#define CP_COMMIT() asm volatile("cp.async.commit_group;" ::: "memory")
#define CP_WAIT2()  asm volatile("cp.async.wait_group 2;" ::: "memory")

__device__ __forceinline__ void ldsm_x4(uint32_t* r, uint32_t addr) {
    asm volatile("ldmatrix.sync.aligned.m8n8.x4.shared.b16 {%0,%1,%2,%3}, [%4];"
                 : "=r"(r[0]), "=r"(r[1]), "=r"(r[2]), "=r"(r[3]) : "r"(addr));
}

__device__ __forceinline__ void mma_bf16(float* c, const uint32_t* a,
                                         const uint32_t* b) {
    asm volatile(
        "mma.sync.aligned.m16n8k16.row.col.f32.bf16.bf16.f32 "
        "{%0,%1,%2,%3}, {%4,%5,%6,%7}, {%8,%9}, {%0,%1,%2,%3};"
        : "+f"(c[0]), "+f"(c[1]), "+f"(c[2]), "+f"(c[3])
        : "r"(a[0]), "r"(a[1]), "r"(a[2]), "r"(a[3]), "r"(b[0]), "r"(b[1]));
}

// ---------------------------------------------------------------------------
// Split-bf16 warp-MMA GEMM: C[m,n] = sum_k A[m,k]*B[n,k], fp32-emulated via
// D += Ah*Bh + Al*Bh + Ah*Bl. CTA tile 128M x 256N, BK=32.
// 4-stage cp.async pipeline (wait_group 2), ONE __syncthreads per iteration:
//   wait -> sync -> issue stage (it+3) [== stage (it-1)%4, vacated by all
//   warps, proven by the sync] -> compute stage it.
// Stage layout: Ah@0 (8K), Al@8K, Bh@16K (16K), Bl@32K (16K) -> 48KB/stage.
// Row = 64B, XOR swizzle off(r,c4)=r*64+((c4^((r>>1)&3))<<4).
// 8 warps: wm = wid&1 (64 M-rows each), wn = wid>>1 (64 N-cols each).
// ---------------------------------------------------------------------------
#define BKI 32
#define NIT (K_TOTAL / BKI)          // 64
#define STG_BYTES 49152
#define NSTG 4
#define SMEM_TOTAL (NSTG * STG_BYTES)   // 192 KB
#define OFF_AL 8192
#define OFF_BH 16384
#define OFF_BL 32768

__global__ __launch_bounds__(256)
void mma_gemm_kernel(const __nv_bfloat16* __restrict__ Ah,
                     const __nv_bfloat16* __restrict__ Al,
                     const __nv_bfloat16* __restrict__ Bh,
                     const __nv_bfloat16* __restrict__ Bl,
                     float* __restrict__ C, int Ntotal) {
    extern __shared__ __align__(1024) char smem[];
    const uint32_t sb = smem_u32(smem);
    const int tid = threadIdx.x;
    const int lane = tid & 31;
    const int wid = tid >> 5;
    const int wm = wid & 1;            // 2 warps along M (64 rows each)
    const int wn = wid >> 1;           // 4 warps along N (64 cols each)
    const int mBase = blockIdx.y * 128;
    const int nBase = blockIdx.x * 256;

    // ---- cp.async mapping: A 2 reps, B 4 reps of 64 rows; 12 cp16/thread ----
    const int ldRow = tid >> 2;        // 0..63
    const int ldC4 = tid & 3;
    const uint32_t sOff =
        (uint32_t)ldRow * 64 + ((((uint32_t)ldC4) ^ ((ldRow >> 1) & 3)) << 4);
    const size_t gRep = (size_t)64 * K_TOTAL;
    const __nv_bfloat16* gAh = Ah + (size_t)(mBase + ldRow) * K_TOTAL + ldC4 * 8;
    const __nv_bfloat16* gAl = Al + (size_t)(mBase + ldRow) * K_TOTAL + ldC4 * 8;
    const __nv_bfloat16* gBh = Bh + (size_t)(nBase + ldRow) * K_TOTAL + ldC4 * 8;
    const __nv_bfloat16* gBl = Bl + (size_t)(nBase + ldRow) * K_TOTAL + ldC4 * 8;

#define ISSUE(sst, k0) do {                                                    \
        cp16((sst) + sOff,                     gAh + (k0));                     \
        cp16((sst) + sOff + 4096,              gAh + (k0) + gRep);              \
        cp16((sst) + OFF_AL + sOff,            gAl + (k0));                     \
        cp16((sst) + OFF_AL + sOff + 4096,     gAl + (k0) + gRep);              \
        cp16((sst) + OFF_BH + sOff,            gBh + (k0));                     \
        cp16((sst) + OFF_BH + sOff + 4096,     gBh + (k0) + gRep);              \
        cp16((sst) + OFF_BH + sOff + 8192,     gBh + (k0) + 2 * gRep);          \
        cp16((sst) + OFF_BH + sOff + 12288,    gBh + (k0) + 3 * gRep);          \
        cp16((sst) + OFF_BL + sOff,            gBl + (k0));                     \
        cp16((sst) + OFF_BL + sOff + 4096,     gBl + (k0) + gRep);              \
        cp16((sst) + OFF_BL + sOff + 8192,     gBl + (k0) + 2 * gRep);          \
        cp16((sst) + OFF_BL + sOff + 12288,    gBl + (k0) + 3 * gRep);          \
    } while (0)

    // ---- precomputed ldmatrix swizzle offsets (relative to stage base) ----
    // A fragment offsets (Al uses identical offsets + OFF_AL constant).
    uint32_t aOff[4][2];
    {
        const int rA = lane & 15;
        const uint32_t aK = (uint32_t)(lane >> 4);     // 0/1
#pragma unroll
        for (int i = 0; i < 4; i++) {
            int row = wm * 64 + i * 16 + rA;
            uint32_t base = (uint32_t)row * 64;
            uint32_t sw = (row >> 1) & 3;
#pragma unroll
            for (int kk = 0; kk < 2; kk++)
                aOff[i][kk] = base + (((aK + (uint32_t)(kk * 2)) ^ sw) << 4);
        }
    }
    uint32_t bOff[4][2];
    {
        const int rB = (lane & 7) + ((lane & 16) ? 8 : 0);
        const uint32_t bK = (uint32_t)((lane >> 3) & 1);
#pragma unroll
        for (int p = 0; p < 4; p++) {
            int row = wn * 64 + p * 16 + rB;
            uint32_t base = (uint32_t)row * 64;
            uint32_t sw = (row >> 1) & 3;
#pragma unroll
            for (int kk = 0; kk < 2; kk++)
                bOff[p][kk] = base + (((bK + (uint32_t)(kk * 2)) ^ sw) << 4);
        }
    }

    float acc[4][8][4];
#pragma unroll
    for (int i = 0; i < 4; i++)
#pragma unroll
        for (int j = 0; j < 8; j++)
#pragma unroll
            for (int v = 0; v < 4; v++) acc[i][j][v] = 0.f;

    // ---- pipeline prologue: 3 stages in flight ----
    ISSUE(sb + 0 * STG_BYTES, 0);
    CP_COMMIT();
    ISSUE(sb + 1 * STG_BYTES, BKI);
    CP_COMMIT();
    ISSUE(sb + 2 * STG_BYTES, 2 * BKI);
    CP_COMMIT();

    for (int it = 0; it < NIT; ++it) {
        CP_WAIT2();
        __syncthreads();

        if (it + 3 < NIT) {
            uint32_t sn = sb + (uint32_t)((it + 3) & 3) * STG_BYTES;
            ISSUE(sn, (it + 3) * BKI);
        }
        CP_COMMIT();

        const uint32_t sst = sb + (uint32_t)(it & 3) * STG_BYTES;
#pragma unroll
        for (int kk = 0; kk < 2; kk++) {           // two k16 halves of BK=32
            uint32_t af[16], af2[16], bf[16];

            // Ah, Bh
#pragma unroll
            for (int i = 0; i < 4; i++)
                ldsm_x4(&af[i * 4], sst + aOff[i][kk]);
#pragma unroll
            for (int p = 0; p < 4; p++)
                ldsm_x4(&bf[p * 4], sst + OFF_BH + bOff[p][kk]);
#pragma unroll
            for (int i = 0; i < 4; i++)
#pragma unroll
                for (int j = 0; j < 8; j++)
                    mma_bf16(acc[i][j], &af[i * 4],
                             &bf[(j >> 1) * 4 + (j & 1) * 2]);

            // Al * Bh
#pragma unroll
            for (int i = 0; i < 4; i++)
                ldsm_x4(&af2[i * 4], sst + OFF_AL + aOff[i][kk]);
#pragma unroll
            for (int i = 0; i < 4; i++)
#pragma unroll
                for (int j = 0; j < 8; j++)
                    mma_bf16(acc[i][j], &af2[i * 4],
                             &bf[(j >> 1) * 4 + (j & 1) * 2]);

            // Ah * Bl (overwrite bf with Bl; af still holds Ah)
#pragma unroll
            for (int p = 0; p < 4; p++)
                ldsm_x4(&bf[p * 4], sst + OFF_BL + bOff[p][kk]);
#pragma unroll
            for (int i = 0; i < 4; i++)
#pragma unroll
                for (int j = 0; j < 8; j++)
                    mma_bf16(acc[i][j], &af[i * 4],
                             &bf[(j >> 1) * 4 + (j & 1) * 2]);
        }
    }

    // ---- epilogue: write C ----
    const int row0 = mBase + wm * 64 + (lane >> 2);
    const int col0 = nBase + wn * 64 + (lane & 3) * 2;
#pragma unroll
    for (int i = 0; i < 4; i++) {
#pragma unroll
        for (int j = 0; j < 8; j++) {
            float* p0 = C + (size_t)(row0 + i * 16) * Ntotal + col0 + j * 8;
            float* p1 = p0 + (size_t)8 * Ntotal;
            *(float2*)p0 = make_float2(acc[i][j][0], acc[i][j][1]);
            *(float2*)p1 = make_float2(acc[i][j][2], acc[i][j][3]);
        }
    }
#undef ISSUE
}

// ---------------------------------------------------------------------------
// fp32 -> (bf16 hi, bf16 lo) split
// ---------------------------------------------------------------------------
__global__ void split_bf16_kernel(const float* __restrict__ src,
                                  __nv_bfloat16* __restrict__ hi,
                                  __nv_bfloat16* __restrict__ lo, int n) {
    int i = blockIdx.x * blockDim.x + threadIdx.x;
    int stride = gridDim.x * blockDim.x;
    for (; i < n; i += stride) {
        float v = src[i];
        __nv_bfloat16 h = __float2bfloat16(v);
        hi[i] = h;
        lo[i] = __float2bfloat16(v - __bfloat162float(h));
    }
}

// ---------------------------------------------------------------------------
// conv_state copy-through
// ---------------------------------------------------------------------------
__global__ void copy_state_kernel(const float4* __restrict__ src,
                                  float4* __restrict__ dst, int n4) {
    int i = blockIdx.x * blockDim.x + threadIdx.x;
    int stride = gridDim.x * blockDim.x;
    for (; i < n4; i += stride) dst[i] = src[i];
}

// ---------------------------------------------------------------------------
// conv + gating epilogue; emits gated as bf16 hi/lo splits directly
// ---------------------------------------------------------------------------
__global__ void conv_epilogue_kernel(const float* __restrict__ proj,
                                     const float* __restrict__ conv_state,
                                     const int* __restrict__ idx,
                                     const float* __restrict__ conv_w,
                                     __nv_bfloat16* __restrict__ ghi,
                                     __nv_bfloat16* __restrict__ glo,
                                     float* __restrict__ out_state) {
    int i = blockIdx.x * blockDim.x + threadIdx.x;
    if (i >= B_SZ * H_SZ) return;
    int b = i >> 11;
    int h = i & (H_SZ - 1);
    int r = idx[b];

    const float* cs = conv_state + ((size_t)r * H_SZ + h) * 3;
    float c0 = cs[0], c1 = cs[1], c2 = cs[2];

    const float* prow = proj + (size_t)b * 3 * H_SZ;
    float Bg = prow[h];
    float Cg = prow[H_SZ + h];
    float x  = prow[2 * H_SZ + h];
    float Bx = Bg * x;

    const float* w = conv_w + h * 4;
    float conv_out = fmaf(c0, w[0], fmaf(c1, w[1], fmaf(c2, w[2], Bx * w[3])));
    float g = Cg * conv_out;

    __nv_bfloat16 gh = __float2bfloat16(g);
    ghi[i] = gh;
    glo[i] = __float2bfloat16(g - __bfloat162float(gh));

    float* os = out_state + ((size_t)r * H_SZ + h) * 3;
    os[0] = c1;
    os[1] = c2;
    os[2] = Bx;
}

// ---------------------------------------------------------------------------
extern "C" void kernel_launch(void* const* d_in, const int* in_sizes, int n_in,
                              void* d_out, int out_size) {
    const float* hidden     = (const float*)d_in[0];
    const float* conv_state = (const float*)d_in[1];
    const int*   idx        = (const int*)d_in[2];
    const float* w_in       = (const float*)d_in[3];
    const float* w_out      = (const float*)d_in[4];
    const float* conv_w     = (const float*)d_in[5];

    float* y         = (float*)d_out;
    float* out_state = y + (size_t)B_SZ * H_SZ;

    void *proj, *hid_hi, *hid_lo, *win_hi, *win_lo, *wout_hi, *wout_lo,
         *gat_hi, *gat_lo;
    cudaGetSymbolAddress(&proj, g_proj);
    cudaGetSymbolAddress(&hid_hi, g_hid_hi);
    cudaGetSymbolAddress(&hid_lo, g_hid_lo);
    cudaGetSymbolAddress(&win_hi, g_win_hi);
    cudaGetSymbolAddress(&win_lo, g_win_lo);
    cudaGetSymbolAddress(&wout_hi, g_wout_hi);
    cudaGetSymbolAddress(&wout_lo, g_wout_lo);
    cudaGetSymbolAddress(&gat_hi, g_gated_hi);
    cudaGetSymbolAddress(&gat_lo, g_gated_lo);

    cudaFuncSetAttribute(mma_gemm_kernel,
                         cudaFuncAttributeMaxDynamicSharedMemorySize,
                         SMEM_TOTAL);

    // 1) bf16 hi/lo splits of inputs/weights
    split_bf16_kernel<<<2048, 256>>>(hidden, (__nv_bfloat16*)hid_hi,
                                     (__nv_bfloat16*)hid_lo, B_SZ * H_SZ);
    split_bf16_kernel<<<4096, 256>>>(w_in, (__nv_bfloat16*)win_hi,
                                     (__nv_bfloat16*)win_lo, 3 * H_SZ * H_SZ);
    split_bf16_kernel<<<2048, 256>>>(w_out, (__nv_bfloat16*)wout_hi,
                                     (__nv_bfloat16*)wout_lo, H_SZ * H_SZ);

    // 2) conv_state copy-through (rows overwritten by epilogue)
    copy_state_kernel<<<4096, 256>>>((const float4*)conv_state,
                                     (float4*)out_state, (P_SZ * H_SZ * 3) / 4);

    // 3) proj = hidden @ w_in^T   [2048 x 6144]
    mma_gemm_kernel<<<dim3((3 * H_SZ) / 256, B_SZ / 128), 256, SMEM_TOTAL>>>(
        (const __nv_bfloat16*)hid_hi, (const __nv_bfloat16*)hid_lo,
        (const __nv_bfloat16*)win_hi, (const __nv_bfloat16*)win_lo,
        (float*)proj, 3 * H_SZ);

    // 4) conv + gate epilogue -> gated (bf16 hi/lo), scatter state rows
    conv_epilogue_kernel<<<(B_SZ * H_SZ + 255) / 256, 256>>>(
        (const float*)proj, conv_state, idx, conv_w,
        (__nv_bfloat16*)gat_hi, (__nv_bfloat16*)gat_lo, out_state);

    // 5) y = gated @ w_out^T   [2048 x 2048]
    mma_gemm_kernel<<<dim3(H_SZ / 256, B_SZ / 128), 256, SMEM_TOTAL>>>(
        (const __nv_bfloat16*)gat_hi, (const __nv_bfloat16*)gat_lo,
        (const __nv_bfloat16*)wout_hi, (const __nv_bfloat16*)wout_lo,
        y, H_SZ);
}

// round 12
// speedup vs baseline: 1.3392x; 1.3359x over previous
#include <cuda_runtime.h>
#include <cuda_fp16.h>
#include <cstdint>

#define B_SZ 2048
#define H_SZ 2048
#define P_SZ 8192
#define K_TOTAL 2048

// ---------------------------------------------------------------------------
// Scratch (__device__ globals; no cudaMalloc allowed)
// ---------------------------------------------------------------------------
__device__ __align__(1024) float g_proj[(size_t)B_SZ * 3 * H_SZ];
__device__ __align__(1024) __half g_hid_hi[(size_t)B_SZ * H_SZ];
__device__ __align__(1024) __half g_hid_lo[(size_t)B_SZ * H_SZ];
__device__ __align__(1024) __half g_win[(size_t)3 * H_SZ * H_SZ];
__device__ __align__(1024) __half g_wout[(size_t)H_SZ * H_SZ];
__device__ __align__(1024) __half g_gated_hi[(size_t)B_SZ * H_SZ];
__device__ __align__(1024) __half g_gated_lo[(size_t)B_SZ * H_SZ];

// ---------------------------------------------------------------------------
// Baseline-PTX helpers (legal on plain sm_103 target)
// ---------------------------------------------------------------------------
__device__ __forceinline__ uint32_t smem_u32(const void* p) {
    uint32_t a;
    asm("{ .reg .u64 t; cvta.to.shared.u64 t, %1; cvt.u32.u64 %0, t; }"
        : "=r"(a) : "l"(p));
    return a;
}

__device__ __forceinline__ void cp16(uint32_t dst, const void* src) {
    asm volatile("cp.async.cg.shared.global [%0], [%1], 16;"
                 :: "r"(dst), "l"(src));
}
#define CP_COMMIT() asm volatile("cp.async.commit_group;" ::: "memory")
#define CP_WAIT2()  asm volatile("cp.async.wait_group 2;" ::: "memory")

__device__ __forceinline__ void ldsm_x4(uint32_t* r, uint32_t addr) {
    asm volatile("ldmatrix.sync.aligned.m8n8.x4.shared.b16 {%0,%1,%2,%3}, [%4];"
                 : "=r"(r[0]), "=r"(r[1]), "=r"(r[2]), "=r"(r[3]) : "r"(addr));
}

__device__ __forceinline__ void mma_fp16(float* c, const uint32_t* a,
                                         const uint32_t* b) {
    asm volatile(
        "mma.sync.aligned.m16n8k16.row.col.f32.f16.f16.f32 "
        "{%0,%1,%2,%3}, {%4,%5,%6,%7}, {%8,%9}, {%0,%1,%2,%3};"
        : "+f"(c[0]), "+f"(c[1]), "+f"(c[2]), "+f"(c[3])
        : "r"(a[0]), "r"(a[1]), "r"(a[2]), "r"(a[3]), "r"(b[0]), "r"(b[1]));
}

// ---------------------------------------------------------------------------
// Split-fp16 2-product GEMM: C[m,n] = sum_k A[m,k]*B[n,k], fp32-emulated via
// D = Ah*B + Al*B  (A = Ah + Al in fp16; B single fp16; dropped err ~2^-12).
// CTA tile 128M x 256N, BK=32. 4-stage cp.async pipeline (wait_group 2),
// ONE __syncthreads per iteration (stage being refilled was vacated by all
// warps before the barrier).
// Stage layout: Ah@0 (8K), Al@8K (8K), B@16K (16K) -> 32KB/stage.
// Row = 64B, XOR swizzle off(r,c4)=r*64+((c4^((r>>1)&3))<<4).
// 8 warps: wm = wid&1 (64 M-rows each), wn = wid>>1 (64 N-cols each).
// ---------------------------------------------------------------------------
#define BKI 32
#define NIT (K_TOTAL / BKI)          // 64
#define STG_BYTES 32768
#define NSTG 4
#define SMEM_TOTAL (NSTG * STG_BYTES)   // 128 KB
#define OFF_AL 8192
#define OFF_B  16384

__global__ __launch_bounds__(256)
void mma_gemm_kernel(const __half* __restrict__ Ah,
                     const __half* __restrict__ Al,
                     const __half* __restrict__ Bm,
                     float* __restrict__ C, int Ntotal) {
    extern __shared__ __align__(1024) char smem[];
    const uint32_t sb = smem_u32(smem);
    const int tid = threadIdx.x;
    const int lane = tid & 31;
    const int wid = tid >> 5;
    const int wm = wid & 1;            // 2 warps along M (64 rows each)
    const int wn = wid >> 1;           // 4 warps along N (64 cols each)
    const int mBase = blockIdx.y * 128;
    const int nBase = blockIdx.x * 256;

    // ---- cp.async mapping: Ah 2 reps, Al 2 reps, B 4 reps; 8 cp16/thread ----
    const int ldRow = tid >> 2;        // 0..63
    const int ldC4 = tid & 3;
    const uint32_t sOff =
        (uint32_t)ldRow * 64 + ((((uint32_t)ldC4) ^ ((ldRow >> 1) & 3)) << 4);
    const size_t gRep = (size_t)64 * K_TOTAL;
    const __half* gAh = Ah + (size_t)(mBase + ldRow) * K_TOTAL + ldC4 * 8;
    const __half* gAl = Al + (size_t)(mBase + ldRow) * K_TOTAL + ldC4 * 8;
    const __half* gB  = Bm + (size_t)(nBase + ldRow) * K_TOTAL + ldC4 * 8;

#define ISSUE(sst, k0) do {                                                    \
        cp16((sst) + sOff,                    gAh + (k0));                      \
        cp16((sst) + sOff + 4096,             gAh + (k0) + gRep);               \
        cp16((sst) + OFF_AL + sOff,           gAl + (k0));                      \
        cp16((sst) + OFF_AL + sOff + 4096,    gAl + (k0) + gRep);               \
        cp16((sst) + OFF_B + sOff,            gB + (k0));                       \
        cp16((sst) + OFF_B + sOff + 4096,     gB + (k0) + gRep);                \
        cp16((sst) + OFF_B + sOff + 8192,     gB + (k0) + 2 * gRep);            \
        cp16((sst) + OFF_B + sOff + 12288,    gB + (k0) + 3 * gRep);            \
    } while (0)

    // ---- precomputed ldmatrix swizzle offsets (relative to stage base) ----
    uint32_t aOff[4][2];
    {
        const int rA = lane & 15;
        const uint32_t aK = (uint32_t)(lane >> 4);     // 0/1
#pragma unroll
        for (int i = 0; i < 4; i++) {
            int row = wm * 64 + i * 16 + rA;
            uint32_t base = (uint32_t)row * 64;
            uint32_t sw = (row >> 1) & 3;
#pragma unroll
            for (int kk = 0; kk < 2; kk++)
                aOff[i][kk] = base + (((aK + (uint32_t)(kk * 2)) ^ sw) << 4);
        }
    }
    uint32_t bOff[4][2];
    {
        const int rB = (lane & 7) + ((lane & 16) ? 8 : 0);
        const uint32_t bK = (uint32_t)((lane >> 3) & 1);
#pragma unroll
        for (int p = 0; p < 4; p++) {
            int row = wn * 64 + p * 16 + rB;
            uint32_t base = (uint32_t)row * 64;
            uint32_t sw = (row >> 1) & 3;
#pragma unroll
            for (int kk = 0; kk < 2; kk++)
                bOff[p][kk] = base + (((bK + (uint32_t)(kk * 2)) ^ sw) << 4);
        }
    }

    float acc[4][8][4];
#pragma unroll
    for (int i = 0; i < 4; i++)
#pragma unroll
        for (int j = 0; j < 8; j++)
#pragma unroll
            for (int v = 0; v < 4; v++) acc[i][j][v] = 0.f;

    // ---- pipeline prologue: 3 stages in flight ----
    ISSUE(sb + 0 * STG_BYTES, 0);
    CP_COMMIT();
    ISSUE(sb + 1 * STG_BYTES, BKI);
    CP_COMMIT();
    ISSUE(sb + 2 * STG_BYTES, 2 * BKI);
    CP_COMMIT();

    for (int it = 0; it < NIT; ++it) {
        CP_WAIT2();
        __syncthreads();

        if (it + 3 < NIT) {
            uint32_t sn = sb + (uint32_t)((it + 3) & 3) * STG_BYTES;
            ISSUE(sn, (it + 3) * BKI);
        }
        CP_COMMIT();

        const uint32_t sst = sb + (uint32_t)(it & 3) * STG_BYTES;
#pragma unroll
        for (int kk = 0; kk < 2; kk++) {           // two k16 halves of BK=32
            uint32_t af[16], af2[16], bf[16];

#pragma unroll
            for (int i = 0; i < 4; i++)
                ldsm_x4(&af[i * 4], sst + aOff[i][kk]);
#pragma unroll
            for (int p = 0; p < 4; p++)
                ldsm_x4(&bf[p * 4], sst + OFF_B + bOff[p][kk]);
#pragma unroll
            for (int i = 0; i < 4; i++)
#pragma unroll
                for (int j = 0; j < 8; j++)
                    mma_fp16(acc[i][j], &af[i * 4],
                             &bf[(j >> 1) * 4 + (j & 1) * 2]);

            // Al * B
#pragma unroll
            for (int i = 0; i < 4; i++)
                ldsm_x4(&af2[i * 4], sst + OFF_AL + aOff[i][kk]);
#pragma unroll
            for (int i = 0; i < 4; i++)
#pragma unroll
                for (int j = 0; j < 8; j++)
                    mma_fp16(acc[i][j], &af2[i * 4],
                             &bf[(j >> 1) * 4 + (j & 1) * 2]);
        }
    }

    // ---- epilogue: write C ----
    const int row0 = mBase + wm * 64 + (lane >> 2);
    const int col0 = nBase + wn * 64 + (lane & 3) * 2;
#pragma unroll
    for (int i = 0; i < 4; i++) {
#pragma unroll
        for (int j = 0; j < 8; j++) {
            float* p0 = C + (size_t)(row0 + i * 16) * Ntotal + col0 + j * 8;
            float* p1 = p0 + (size_t)8 * Ntotal;
            *(float2*)p0 = make_float2(acc[i][j][0], acc[i][j][1]);
            *(float2*)p1 = make_float2(acc[i][j][2], acc[i][j][3]);
        }
    }
#undef ISSUE
}

// ---------------------------------------------------------------------------
// fp32 -> (fp16 hi, fp16 lo) split
// ---------------------------------------------------------------------------
__global__ void split_fp16_kernel(const float* __restrict__ src,
                                  __half* __restrict__ hi,
                                  __half* __restrict__ lo, int n) {
    int i = blockIdx.x * blockDim.x + threadIdx.x;
    int stride = gridDim.x * blockDim.x;
    for (; i < n; i += stride) {
        float v = src[i];
        __half h = __float2half_rn(v);
        hi[i] = h;
        lo[i] = __float2half_rn(v - __half2float(h));
    }
}

// ---------------------------------------------------------------------------
// fp32 -> fp16 (single rounding; weights)
// ---------------------------------------------------------------------------
__global__ void cvt_fp16_kernel(const float* __restrict__ src,
                                __half* __restrict__ dst, int n) {
    int i = blockIdx.x * blockDim.x + threadIdx.x;
    int stride = gridDim.x * blockDim.x;
    for (; i < n; i += stride) dst[i] = __float2half_rn(src[i]);
}

// ---------------------------------------------------------------------------
// conv_state copy-through
// ---------------------------------------------------------------------------
__global__ void copy_state_kernel(const float4* __restrict__ src,
                                  float4* __restrict__ dst, int n4) {
    int i = blockIdx.x * blockDim.x + threadIdx.x;
    int stride = gridDim.x * blockDim.x;
    for (; i < n4; i += stride) dst[i] = src[i];
}

// ---------------------------------------------------------------------------
// conv + gating epilogue; emits gated as fp16 hi/lo splits directly
// ---------------------------------------------------------------------------
__global__ void conv_epilogue_kernel(const float* __restrict__ proj,
                                     const float* __restrict__ conv_state,
                                     const int* __restrict__ idx,
                                     const float* __restrict__ conv_w,
                                     __half* __restrict__ ghi,
                                     __half* __restrict__ glo,
                                     float* __restrict__ out_state) {
    int i = blockIdx.x * blockDim.x + threadIdx.x;
    if (i >= B_SZ * H_SZ) return;
    int b = i >> 11;
    int h = i & (H_SZ - 1);
    int r = idx[b];

    const float* cs = conv_state + ((size_t)r * H_SZ + h) * 3;
    float c0 = cs[0], c1 = cs[1], c2 = cs[2];

    const float* prow = proj + (size_t)b * 3 * H_SZ;
    float Bg = prow[h];
    float Cg = prow[H_SZ + h];
    float x  = prow[2 * H_SZ + h];
    float Bx = Bg * x;

    const float* w = conv_w + h * 4;
    float conv_out = fmaf(c0, w[0], fmaf(c1, w[1], fmaf(c2, w[2], Bx * w[3])));
    float g = Cg * conv_out;

    __half gh = __float2half_rn(g);
    ghi[i] = gh;
    glo[i] = __float2half_rn(g - __half2float(gh));

    float* os = out_state + ((size_t)r * H_SZ + h) * 3;
    os[0] = c1;
    os[1] = c2;
    os[2] = Bx;
}

// ---------------------------------------------------------------------------
extern "C" void kernel_launch(void* const* d_in, const int* in_sizes, int n_in,
                              void* d_out, int out_size) {
    const float* hidden     = (const float*)d_in[0];
    const float* conv_state = (const float*)d_in[1];
    const int*   idx        = (const int*)d_in[2];
    const float* w_in       = (const float*)d_in[3];
    const float* w_out      = (const float*)d_in[4];
    const float* conv_w     = (const float*)d_in[5];

    float* y         = (float*)d_out;
    float* out_state = y + (size_t)B_SZ * H_SZ;

    void *proj, *hid_hi, *hid_lo, *win, *wout, *gat_hi, *gat_lo;
    cudaGetSymbolAddress(&proj, g_proj);
    cudaGetSymbolAddress(&hid_hi, g_hid_hi);
    cudaGetSymbolAddress(&hid_lo, g_hid_lo);
    cudaGetSymbolAddress(&win, g_win);
    cudaGetSymbolAddress(&wout, g_wout);
    cudaGetSymbolAddress(&gat_hi, g_gated_hi);
    cudaGetSymbolAddress(&gat_lo, g_gated_lo);

    cudaFuncSetAttribute(mma_gemm_kernel,
                         cudaFuncAttributeMaxDynamicSharedMemorySize,
                         SMEM_TOTAL);

    // 1) fp16 conversions
    split_fp16_kernel<<<2048, 256>>>(hidden, (__half*)hid_hi, (__half*)hid_lo,
                                     B_SZ * H_SZ);
    cvt_fp16_kernel<<<4096, 256>>>(w_in, (__half*)win, 3 * H_SZ * H_SZ);
    cvt_fp16_kernel<<<2048, 256>>>(w_out, (__half*)wout, H_SZ * H_SZ);

    // 2) conv_state copy-through (rows overwritten by epilogue)
    copy_state_kernel<<<4096, 256>>>((const float4*)conv_state,
                                     (float4*)out_state, (P_SZ * H_SZ * 3) / 4);

    // 3) proj = hidden @ w_in^T   [2048 x 6144]
    mma_gemm_kernel<<<dim3((3 * H_SZ) / 256, B_SZ / 128), 256, SMEM_TOTAL>>>(
        (const __half*)hid_hi, (const __half*)hid_lo,
        (const __half*)win, (float*)proj, 3 * H_SZ);

    // 4) conv + gate epilogue -> gated (fp16 hi/lo), scatter state rows
    conv_epilogue_kernel<<<(B_SZ * H_SZ + 255) / 256, 256>>>(
        (const float*)proj, conv_state, idx, conv_w,
        (__half*)gat_hi, (__half*)gat_lo, out_state);

    // 5) y = gated @ w_out^T   [2048 x 2048]
    mma_gemm_kernel<<<dim3(H_SZ / 256, B_SZ / 128), 256, SMEM_TOTAL>>>(
        (const __half*)gat_hi, (const __half*)gat_lo,
        (const __half*)wout, y, H_SZ);
}